// round 7
// baseline (speedup 1.0000x reference)
#include <cuda_runtime.h>
#include <math.h>
#include <stdint.h>

// Problem constants
#define Tt  2048
#define Bb  2
#define Ee  1024
#define Hh  16
#define HDd 64
#define BH  32          // Bb*Hh
#define MR  4096        // Tt*Bb rows

// -------- device scratch (allocation-free: static device globals) ----------
__device__ __align__(16) float g_q [(size_t)BH * Tt * HDd];   // 16 MB (bh,t,hd), q pre-scaled 1/8
__device__ __align__(16) float g_k [(size_t)BH * Tt * HDd];   // 16 MB (bh,t,hd)
__device__ __align__(16) float g_vt[(size_t)BH * HDd * Tt];   // 16 MB (bh,hd,t)  V transposed
__device__ __align__(16) float g_s [(size_t)BH * Tt * Tt];    // 512 MB unnormalized exp(scores)
__device__ __align__(16) float g_ao[(size_t)MR * Ee];         // 16 MB rows = t*B+b
__device__ __align__(16) float g_part[(size_t)BH * Tt * 32];  // 8 MB per-row expsum partials
__device__            float g_rinv[(size_t)BH * Tt];          // 1/rowsum

// ============================================================================
// tf32 helpers
// ============================================================================
__device__ __forceinline__ uint32_t f2tf(float x) {
    uint32_t u;
    asm("cvt.rna.tf32.f32 %0, %1;" : "=r"(u) : "f"(x));
    return u;
}

__device__ __forceinline__ void mma8(float c[4], const uint32_t a[4],
                                     uint32_t b0, uint32_t b1) {
    asm volatile(
        "mma.sync.aligned.m16n8k8.row.col.f32.tf32.tf32.f32 "
        "{%0,%1,%2,%3}, {%4,%5,%6,%7}, {%8,%9}, {%0,%1,%2,%3};"
        : "+f"(c[0]), "+f"(c[1]), "+f"(c[2]), "+f"(c[3])
        : "r"(a[0]), "r"(a[1]), "r"(a[2]), "r"(a[3]), "r"(b0), "r"(b1));
}

// ============================================================================
// NT tf32 tensor-core GEMM core.
//   C[m,n] = sum_k A[m,k] * B[n,k]   (both K-contiguous row-major)
// Block: 256 threads (8 warps, 4x2 grid). Block tile 128 x BN (BN = 64|128).
// Warp tile 32 x (BN/2) = 2 mtiles(16) x NT ntiles(8). K chunked by 32.
// tf32 conversion (cvt.rna) happens once at the smem store.
// ============================================================================
template<int BN>
__device__ __forceinline__ void gemm_nt_tf32(
    const float* __restrict__ A, const float* __restrict__ B,
    int lda, int ldb, int K,
    float acc[2][BN / 16][4])
{
    constexpr int NT = BN / 16;
    constexpr int P  = 36;            // smem pitch (floats): conflict-free frags
    constexpr int BPASS = BN / 32;

    __shared__ float sA[128 * P];
    __shared__ float sB[BN * P];

    const int tid  = threadIdx.x;
    const int lane = tid & 31;
    const int g    = lane >> 2, q = lane & 3;
    const int w    = tid >> 5;
    const int wm   = w & 3, wn = w >> 2;

    const int ar = tid >> 3;          // 0..31
    const int ac = (tid & 7) << 2;    // 0,4,...,28

    const float* Ap = A + (size_t)ar * lda + ac;
    const float* Bp = B + (size_t)ar * ldb + ac;

    float4 ra[4], rb[BPASS];
#pragma unroll
    for (int p = 0; p < 4; p++)     ra[p] = *(const float4*)(Ap + (size_t)(p * 32) * lda);
#pragma unroll
    for (int p = 0; p < BPASS; p++) rb[p] = *(const float4*)(Bp + (size_t)(p * 32) * ldb);

    for (int k0 = 0; k0 < K; k0 += 32) {
        // stage (tf32-rounded) into smem
#pragma unroll
        for (int p = 0; p < 4; p++) {
            float* d = &sA[(ar + p * 32) * P + ac];
            d[0] = __uint_as_float(f2tf(ra[p].x));
            d[1] = __uint_as_float(f2tf(ra[p].y));
            d[2] = __uint_as_float(f2tf(ra[p].z));
            d[3] = __uint_as_float(f2tf(ra[p].w));
        }
#pragma unroll
        for (int p = 0; p < BPASS; p++) {
            float* d = &sB[(ar + p * 32) * P + ac];
            d[0] = __uint_as_float(f2tf(rb[p].x));
            d[1] = __uint_as_float(f2tf(rb[p].y));
            d[2] = __uint_as_float(f2tf(rb[p].z));
            d[3] = __uint_as_float(f2tf(rb[p].w));
        }
        __syncthreads();

        // prefetch next chunk while computing on this one
        if (k0 + 32 < K) {
            const float* An = Ap + k0 + 32;
            const float* Bn = Bp + k0 + 32;
#pragma unroll
            for (int p = 0; p < 4; p++)     ra[p] = *(const float4*)(An + (size_t)(p * 32) * lda);
#pragma unroll
            for (int p = 0; p < BPASS; p++) rb[p] = *(const float4*)(Bn + (size_t)(p * 32) * ldb);
        }

#pragma unroll
        for (int ks = 0; ks < 4; ks++) {
            uint32_t af[2][4];
#pragma unroll
            for (int i = 0; i < 2; i++) {
                const float* pa = &sA[(wm * 32 + i * 16 + g) * P + ks * 8 + q];
                af[i][0] = __float_as_uint(pa[0]);
                af[i][1] = __float_as_uint(pa[8 * P]);
                af[i][2] = __float_as_uint(pa[4]);
                af[i][3] = __float_as_uint(pa[8 * P + 4]);
            }
#pragma unroll
            for (int j = 0; j < NT; j++) {
                const float* pb = &sB[(wn * (BN / 2) + j * 8 + g) * P + ks * 8 + q];
                uint32_t b0 = __float_as_uint(pb[0]);
                uint32_t b1 = __float_as_uint(pb[4]);
                mma8(acc[0][j], af[0], b0, b1);
                mma8(acc[1][j], af[1], b0, b1);
            }
        }
        __syncthreads();
    }
}

// C-fragment coordinate helpers (per thread):
//   row_local(i,ch) = wm*32 + i*16 + ch*8 + g
//   col_local(j,parity) = wn*(BN/2) + j*8 + q*2 + parity
//   acc[i][j][ch*2+parity]

// ============================================================================
// Kernel 1: fused Q/K/V projection. Gate path is a provable no-op (TOPK==E).
// X: (T,B,E) rows r=t*B+b.  W: (3E,E).  q,k -> (bh,t,hd) (q scaled 1/8),
// v -> transposed (bh,hd,t) so AV is an NT GEMM.
// grid = (MR/128, Ee/128, 3), block = 256
// ============================================================================
__global__ void __launch_bounds__(256) qkv_kernel(
    const float* __restrict__ q_in, const float* __restrict__ k_in,
    const float* __restrict__ v_in, const float* __restrict__ wmat,
    const float* __restrict__ bias)
{
    const int mat = blockIdx.z;
    const float* X = (mat == 0) ? q_in : (mat == 1) ? k_in : v_in;
    const float* W = wmat + (size_t)mat * Ee * Ee;
    const float* bp = bias + mat * Ee;
    const int m0 = blockIdx.x * 128, n0 = blockIdx.y * 128;

    float acc[2][8][4] = {};
    gemm_nt_tf32<128>(X + (size_t)m0 * Ee, W + (size_t)n0 * Ee, Ee, Ee, Ee, acc);

    const int lane = threadIdx.x & 31, g = lane >> 2, q = lane & 3;
    const int w = threadIdx.x >> 5, wm = w & 3, wn = w >> 2;

#pragma unroll
    for (int i = 0; i < 2; i++) {
#pragma unroll
        for (int ch = 0; ch < 2; ch++) {
            const int r = m0 + wm * 32 + i * 16 + ch * 8 + g;  // = t*B + b
            const int t = r >> 1, b = r & 1;
#pragma unroll
            for (int j = 0; j < 8; j++) {
                const int o = n0 + wn * 64 + j * 8 + q * 2;
                float v0 = acc[i][j][ch * 2 + 0] + bp[o];
                float v1 = acc[i][j][ch * 2 + 1] + bp[o + 1];
                const int h = o >> 6, hd = o & 63;
                const int bh = b * Hh + h;
                if (mat == 0) {
                    float2 p = make_float2(v0 * 0.125f, v1 * 0.125f);
                    *(float2*)&g_q[((size_t)bh * Tt + t) * HDd + hd] = p;
                } else if (mat == 1) {
                    float2 p = make_float2(v0, v1);
                    *(float2*)&g_k[((size_t)bh * Tt + t) * HDd + hd] = p;
                } else {
                    g_vt[((size_t)bh * HDd + hd    ) * Tt + t] = v0;
                    g_vt[((size_t)bh * HDd + hd + 1) * Tt + t] = v1;
                }
            }
        }
    }
}

// ============================================================================
// Kernel 2: scores + exp + deterministic per-row expsum partials.
// Writes exp(q.k) unnormalized (logits are O(1): max-subtraction is a no-op
// after normalization; fp32 exp cannot overflow here).
// grid = (Tt/128, Tt/128, BH), block = 256
// ============================================================================
__global__ void __launch_bounds__(256) scores_kernel()
{
    const int bh = blockIdx.z;
    const int m0 = blockIdx.x * 128, n0 = blockIdx.y * 128;
    const float* Q = g_q + (size_t)bh * Tt * HDd;
    const float* Kp = g_k + (size_t)bh * Tt * HDd;

    float acc[2][8][4] = {};
    gemm_nt_tf32<128>(Q + (size_t)m0 * HDd, Kp + (size_t)n0 * HDd, HDd, HDd, HDd, acc);

    const int lane = threadIdx.x & 31, g = lane >> 2, q = lane & 3;
    const int w = threadIdx.x >> 5, wm = w & 3, wn = w >> 2;
    float* S = g_s + (size_t)bh * Tt * Tt;

#pragma unroll
    for (int i = 0; i < 2; i++) {
#pragma unroll
        for (int ch = 0; ch < 2; ch++) {
            const int row = m0 + wm * 32 + i * 16 + ch * 8 + g;
            float rs = 0.f;
#pragma unroll
            for (int j = 0; j < 8; j++) {
                float e0 = __expf(acc[i][j][ch * 2 + 0]);
                float e1 = __expf(acc[i][j][ch * 2 + 1]);
                rs += e0 + e1;
                const int col = n0 + wn * 64 + j * 8 + q * 2;
                *(float2*)&S[(size_t)row * Tt + col] = make_float2(e0, e1);
            }
            rs += __shfl_xor_sync(0xffffffffu, rs, 1);
            rs += __shfl_xor_sync(0xffffffffu, rs, 2);
            if (q == 0)
                g_part[((size_t)bh * Tt + row) * 32 + blockIdx.y * 2 + wn] = rs;
        }
    }
}

// ============================================================================
// Kernel 3: reduce 32 partials per row -> 1/rowsum. grid = BH*Tt/256
// ============================================================================
__global__ void rinv_kernel()
{
    const int r = blockIdx.x * 256 + threadIdx.x;
    const float* p = &g_part[(size_t)r * 32];
    float s = 0.f;
#pragma unroll
    for (int i = 0; i < 32; i++) s += p[i];
    g_rinv[r] = 1.0f / s;
}

// ============================================================================
// Kernel 4: attn_weights[b,t,s] = (1/H) * sum_h exp_s[bh,t,s] * rinv[bh,t]
// One block (512 thr) per (b,t).
// ============================================================================
__global__ void headmean_kernel(float* __restrict__ attnw)
{
    const int bt = blockIdx.x;            // b*Tt + t
    const int b = bt >> 11, t = bt & (Tt - 1);
    const int c = threadIdx.x;            // float4 column group
    float4 s = make_float4(0.f, 0.f, 0.f, 0.f);
#pragma unroll
    for (int h = 0; h < Hh; h++) {
        const int bh = b * Hh + h;
        const float iv = g_rinv[(size_t)bh * Tt + t];
        const float4 x = ((const float4*)(g_s + ((size_t)bh * Tt + t) * Tt))[c];
        s.x += x.x * iv; s.y += x.y * iv; s.z += x.z * iv; s.w += x.w * iv;
    }
    const float m = 1.0f / (float)Hh;
    s.x *= m; s.y *= m; s.z *= m; s.w *= m;
    ((float4*)(attnw + (size_t)bt * Tt))[c] = s;
}

// ============================================================================
// Kernel 5: ao = softmax(S) @ V = diag(rinv) * expS @ Vt^T  (NT GEMM, BN=64)
// grid = (Tt/128, 1, BH), block = 256. Writes (t*B+b, h*64+hd) layout.
// ============================================================================
__global__ void __launch_bounds__(256) av_kernel()
{
    const int bh = blockIdx.z;
    const int m0 = blockIdx.x * 128;
    const float* A = g_s + (size_t)bh * Tt * Tt + (size_t)m0 * Tt;
    const float* B = g_vt + (size_t)bh * HDd * Tt;

    float acc[2][4][4] = {};
    gemm_nt_tf32<64>(A, B, Tt, Tt, Tt, acc);

    const int lane = threadIdx.x & 31, g = lane >> 2, q = lane & 3;
    const int w = threadIdx.x >> 5, wm = w & 3, wn = w >> 2;
    const int b = bh >> 4, h = bh & 15;

#pragma unroll
    for (int i = 0; i < 2; i++) {
#pragma unroll
        for (int ch = 0; ch < 2; ch++) {
            const int t = m0 + wm * 32 + i * 16 + ch * 8 + g;
            const float iv = g_rinv[(size_t)bh * Tt + t];
#pragma unroll
            for (int j = 0; j < 4; j++) {
                const int col = wn * 32 + j * 8 + q * 2;
                float2 p = make_float2(acc[i][j][ch * 2 + 0] * iv,
                                       acc[i][j][ch * 2 + 1] * iv);
                *(float2*)&g_ao[((size_t)t * Bb + b) * Ee + h * HDd + col] = p;
            }
        }
    }
}

// ============================================================================
// Kernel 6: out projection (out DGL layer is also a plain affine map).
// grid = (MR/128, Ee/128), block = 256 -> d_out directly
// ============================================================================
__global__ void __launch_bounds__(256) outproj_kernel(
    const float* __restrict__ ow, const float* __restrict__ ob,
    float* __restrict__ out)
{
    const int m0 = blockIdx.x * 128, n0 = blockIdx.y * 128;
    float acc[2][8][4] = {};
    gemm_nt_tf32<128>(g_ao + (size_t)m0 * Ee, ow + (size_t)n0 * Ee, Ee, Ee, Ee, acc);

    const int lane = threadIdx.x & 31, g = lane >> 2, q = lane & 3;
    const int w = threadIdx.x >> 5, wm = w & 3, wn = w >> 2;

#pragma unroll
    for (int i = 0; i < 2; i++) {
#pragma unroll
        for (int ch = 0; ch < 2; ch++) {
            const int r = m0 + wm * 32 + i * 16 + ch * 8 + g;
#pragma unroll
            for (int j = 0; j < 8; j++) {
                const int o = n0 + wn * 64 + j * 8 + q * 2;
                float2 p = make_float2(acc[i][j][ch * 2 + 0] + ob[o],
                                       acc[i][j][ch * 2 + 1] + ob[o + 1]);
                *(float2*)&out[(size_t)r * Ee + o] = p;
            }
        }
    }
}

// ============================================================================
extern "C" void kernel_launch(void* const* d_in, const int* in_sizes, int n_in,
                              void* d_out, int out_size) {
    const float* query = (const float*)d_in[0];
    const float* key   = (const float*)d_in[1];
    const float* value = (const float*)d_in[2];
    const float* ipw   = (const float*)d_in[3];   // (3E, E)
    const float* ipb   = (const float*)d_in[4];   // (3E,)
    const float* ow    = (const float*)d_in[5];   // (E, E)
    const float* ob    = (const float*)d_in[6];   // (E,)
    // d_in[7..12]: gate params — provably unused (TOPK == E makes the top-k
    // mask all-ones, so every DGL layer is a plain linear).
    (void)in_sizes; (void)n_in; (void)out_size;

    float* out   = (float*)d_out;                       // attn_output (T,B,E)
    float* attnw = out + (size_t)Tt * Bb * Ee;          // attn_weights (B,T,T)

    qkv_kernel   <<<dim3(MR / 128, Ee / 128, 3), 256>>>(query, key, value, ipw, ipb);
    scores_kernel<<<dim3(Tt / 128, Tt / 128, BH), 256>>>();
    rinv_kernel  <<<(BH * Tt) / 256, 256>>>();
    headmean_kernel<<<Bb * Tt, 512>>>(attnw);
    av_kernel    <<<dim3(Tt / 128, 1, BH), 256>>>();
    outproj_kernel<<<dim3(MR / 128, Ee / 128), 256>>>(ow, ob, out);
}

// round 9
// speedup vs baseline: 1.2819x; 1.2819x over previous
#include <cuda_runtime.h>
#include <cuda_fp16.h>
#include <math.h>
#include <stdint.h>

// Problem constants
#define Tt  2048
#define Bb  2
#define Ee  1024
#define Hh  16
#define HDd 64
#define BH  32          // Bb*Hh
#define MR  4096        // Tt*Bb rows

// -------- device scratch (allocation-free: static device globals) ----------
__device__ __align__(16) __half g_xh[3][(size_t)MR * Ee];    // 24 MB fp16 q/k/v inputs
__device__ __align__(16) __half g_wh[(size_t)3 * Ee * Ee];   //  6 MB fp16 in_proj_w
__device__ __align__(16) __half g_owh[(size_t)Ee * Ee];      //  2 MB fp16 out_w
__device__ __align__(16) __half g_qh[(size_t)BH * Tt * HDd]; //  8 MB (bh,t,hd), q*0.125
__device__ __align__(16) __half g_kh[(size_t)BH * Tt * HDd]; //  8 MB
__device__ __align__(16) __half g_vth[(size_t)BH * HDd * Tt];//  8 MB (bh,hd,t)
__device__ __align__(16) __half g_sh[(size_t)BH * Tt * Tt];  // 256 MB unnormalized exp(scores)
__device__ __align__(16) __half g_aoh[(size_t)MR * Ee];      //  8 MB rows = t*B+b
__device__ __align__(16) float  g_part[(size_t)BH * Tt * 32];//  8 MB rowsum partials
__device__            float  g_rinv[(size_t)BH * Tt];        // 1/rowsum

// ============================================================================
// fp16 mma: D(f32) += A(f16) * B(f16), m16n8k16, row.col
// ============================================================================
__device__ __forceinline__ void mma16(float c[4], const uint32_t a[4],
                                      uint32_t b0, uint32_t b1) {
    asm volatile(
        "mma.sync.aligned.m16n8k16.row.col.f32.f16.f16.f32 "
        "{%0,%1,%2,%3}, {%4,%5,%6,%7}, {%8,%9}, {%0,%1,%2,%3};"
        : "+f"(c[0]), "+f"(c[1]), "+f"(c[2]), "+f"(c[3])
        : "r"(a[0]), "r"(a[1]), "r"(a[2]), "r"(a[3]), "r"(b0), "r"(b1));
}

// ============================================================================
// NT fp16 tensor-core GEMM core.
//   C[m,n] = sum_k A[m,k] * B[n,k]   (both K-contiguous row-major, fp16)
// Block: 256 threads (8 warps, 4x2). Block tile 128 x BN (BN = 64|128).
// Warp tile 32 x (BN/2). K chunked by 32 halves, register double-buffered.
// Pitch-40 half smem rows: bank = (g*20 + q) mod 32, all 32 lanes distinct.
// ============================================================================
template<int BN>
__device__ __forceinline__ void gemm_nt_f16(
    const __half* __restrict__ A, const __half* __restrict__ B,
    int lda, int ldb, int K,
    float acc[2][BN / 16][4])
{
    constexpr int NT = BN / 16;
    constexpr int P  = 40;               // halves per smem row (80 B)
    constexpr int BPASS = BN / 64;       // 2 for BN=128, 1 for BN=64

    __shared__ __align__(16) __half sA[128 * P];
    __shared__ __align__(16) __half sB[BN * P];

    const int tid  = threadIdx.x;
    const int lane = tid & 31;
    const int g    = lane >> 2, q = lane & 3;
    const int w    = tid >> 5;
    const int wm   = w & 3, wn = w >> 2;

    const int r0 = tid >> 2;             // 0..63
    const int c0 = (tid & 3) * 8;        // 0,8,16,24 halves (16B groups)

    const __half* Ap = A + (size_t)r0 * lda + c0;
    const __half* Bp = B + (size_t)r0 * ldb + c0;

    float4 ra[2], rb[BPASS];
    ra[0] = *(const float4*)Ap;
    ra[1] = *(const float4*)(Ap + (size_t)64 * lda);
#pragma unroll
    for (int p = 0; p < BPASS; p++) rb[p] = *(const float4*)(Bp + (size_t)(p * 64) * ldb);

    for (int k0 = 0; k0 < K; k0 += 32) {
        *(float4*)&sA[(r0     ) * P + c0] = ra[0];
        *(float4*)&sA[(r0 + 64) * P + c0] = ra[1];
#pragma unroll
        for (int p = 0; p < BPASS; p++)
            *(float4*)&sB[(r0 + p * 64) * P + c0] = rb[p];
        __syncthreads();

        if (k0 + 32 < K) {                       // prefetch next chunk
            const __half* An = Ap + k0 + 32;
            const __half* Bn = Bp + k0 + 32;
            ra[0] = *(const float4*)An;
            ra[1] = *(const float4*)(An + (size_t)64 * lda);
#pragma unroll
            for (int p = 0; p < BPASS; p++)
                rb[p] = *(const float4*)(Bn + (size_t)(p * 64) * ldb);
        }

#pragma unroll
        for (int kb = 0; kb < 2; kb++) {         // two k16 steps per chunk
            uint32_t af[2][4];
#pragma unroll
            for (int i = 0; i < 2; i++) {
                const __half* pa = &sA[(wm * 32 + i * 16 + g) * P + kb * 16 + q * 2];
                af[i][0] = *(const uint32_t*)pa;
                af[i][1] = *(const uint32_t*)(pa + 8 * P);
                af[i][2] = *(const uint32_t*)(pa + 8);
                af[i][3] = *(const uint32_t*)(pa + 8 * P + 8);
            }
#pragma unroll
            for (int j = 0; j < NT; j++) {
                const __half* pb = &sB[(wn * (BN / 2) + j * 8 + g) * P + kb * 16 + q * 2];
                uint32_t b0 = *(const uint32_t*)pb;
                uint32_t b1 = *(const uint32_t*)(pb + 8);
                mma16(acc[0][j], af[0], b0, b1);
                mma16(acc[1][j], af[1], b0, b1);
            }
        }
        __syncthreads();
    }
}
// C fragment coords: row = wm*32 + i*16 + ch*8 + g ; col = wn*(BN/2) + j*8 + q*2 (+parity)
// value = acc[i][j][ch*2 + parity]

// ============================================================================
// Kernel 0: fp32 -> fp16 conversion of inputs + weights (one pass).
// Gate params (d_in 7..12) are provably unused: TOPK == E -> all-ones mask,
// so every DGL layer is a plain affine projection.
// ============================================================================
__global__ void prep_kernel(const float* __restrict__ q, const float* __restrict__ k,
                            const float* __restrict__ v, const float* __restrict__ w,
                            const float* __restrict__ ow) {
    const size_t i  = (size_t)blockIdx.x * 256 + threadIdx.x;  // float4 index
    const size_t NX = (size_t)MR * Ee / 4;                     // 1M per input
    const size_t NW = (size_t)3 * Ee * Ee / 4;                 // 768K
    float4 x; __half* dst;
    if (i < NX)          { x = ((const float4*)q)[i];          dst = g_xh[0] + i * 4; }
    else if (i < 2 * NX) { x = ((const float4*)k)[i - NX];     dst = g_xh[1] + (i - NX) * 4; }
    else if (i < 3 * NX) { x = ((const float4*)v)[i - 2 * NX]; dst = g_xh[2] + (i - 2 * NX) * 4; }
    else if (i < 3 * NX + NW) {
        size_t j = i - 3 * NX;      x = ((const float4*)w)[j];  dst = g_wh + j * 4;
    } else {
        size_t j = i - 3 * NX - NW; x = ((const float4*)ow)[j]; dst = g_owh + j * 4;
    }
    *(__half2*)(dst)     = __floats2half2_rn(x.x, x.y);
    *(__half2*)(dst + 2) = __floats2half2_rn(x.z, x.w);
}

// ============================================================================
// Kernel 1: QKV projection. grid (MR/128, Ee/128, 3), 256 thr.
// q,k -> (bh,t,hd) fp16 (q scaled 1/8); v -> transposed (bh,hd,t) fp16.
// ============================================================================
__global__ void __launch_bounds__(256) qkv_kernel(const float* __restrict__ bias) {
    const int mat = blockIdx.z;
    const int m0 = blockIdx.x * 128, n0 = blockIdx.y * 128;
    const float* bp = bias + mat * Ee;

    float acc[2][8][4] = {};
    gemm_nt_f16<128>(g_xh[mat] + (size_t)m0 * Ee,
                     g_wh + (size_t)mat * Ee * Ee + (size_t)n0 * Ee, Ee, Ee, Ee, acc);

    const int lane = threadIdx.x & 31, g = lane >> 2, q = lane & 3;
    const int w = threadIdx.x >> 5, wm = w & 3, wn = w >> 2;

#pragma unroll
    for (int i = 0; i < 2; i++) {
#pragma unroll
        for (int ch = 0; ch < 2; ch++) {
            const int r = m0 + wm * 32 + i * 16 + ch * 8 + g;  // = t*B + b
            const int t = r >> 1, b = r & 1;
#pragma unroll
            for (int j = 0; j < 8; j++) {
                const int o = n0 + wn * 64 + j * 8 + q * 2;
                float v0 = acc[i][j][ch * 2 + 0] + bp[o];
                float v1 = acc[i][j][ch * 2 + 1] + bp[o + 1];
                const int h = o >> 6, hd = o & 63;
                const int bh = b * Hh + h;
                if (mat == 0) {
                    *(__half2*)&g_qh[((size_t)bh * Tt + t) * HDd + hd] =
                        __floats2half2_rn(v0 * 0.125f, v1 * 0.125f);
                } else if (mat == 1) {
                    *(__half2*)&g_kh[((size_t)bh * Tt + t) * HDd + hd] =
                        __floats2half2_rn(v0, v1);
                } else {
                    g_vth[((size_t)bh * HDd + hd    ) * Tt + t] = __float2half_rn(v0);
                    g_vth[((size_t)bh * HDd + hd + 1) * Tt + t] = __float2half_rn(v1);
                }
            }
        }
    }
}

// ============================================================================
// Kernel 2: scores + exp + deterministic rowsum partials.
// Unnormalized exp is safe: logits are O(1) (max-subtract is a no-op after
// normalization; exp <= ~60 fits fp16 range easily).
// grid (16, 16, BH), 256 thr.
// ============================================================================
__global__ void __launch_bounds__(256) scores_kernel() {
    const int bh = blockIdx.z;
    const int m0 = blockIdx.x * 128, n0 = blockIdx.y * 128;

    float acc[2][8][4] = {};
    gemm_nt_f16<128>(g_qh + (size_t)bh * Tt * HDd + (size_t)m0 * HDd,
                     g_kh + (size_t)bh * Tt * HDd + (size_t)n0 * HDd,
                     HDd, HDd, HDd, acc);

    const int lane = threadIdx.x & 31, g = lane >> 2, q = lane & 3;
    const int w = threadIdx.x >> 5, wm = w & 3, wn = w >> 2;
    __half* S = g_sh + (size_t)bh * Tt * Tt;

#pragma unroll
    for (int i = 0; i < 2; i++) {
#pragma unroll
        for (int ch = 0; ch < 2; ch++) {
            const int row = m0 + wm * 32 + i * 16 + ch * 8 + g;
            float rs = 0.f;
#pragma unroll
            for (int j = 0; j < 8; j++) {
                float e0 = __expf(acc[i][j][ch * 2 + 0]);
                float e1 = __expf(acc[i][j][ch * 2 + 1]);
                rs += e0 + e1;
                const int col = n0 + wn * 64 + j * 8 + q * 2;
                *(__half2*)&S[(size_t)row * Tt + col] = __floats2half2_rn(e0, e1);
            }
            rs += __shfl_xor_sync(0xffffffffu, rs, 1);
            rs += __shfl_xor_sync(0xffffffffu, rs, 2);
            if (q == 0)
                g_part[((size_t)bh * Tt + row) * 32 + blockIdx.y * 2 + wn] = rs;
        }
    }
}

// ============================================================================
// Kernel 3: reduce 32 partials per row -> 1/rowsum.
// ============================================================================
__global__ void rinv_kernel() {
    const int r = blockIdx.x * 256 + threadIdx.x;
    const float* p = &g_part[(size_t)r * 32];
    float s = 0.f;
#pragma unroll
    for (int i = 0; i < 32; i++) s += p[i];
    g_rinv[r] = 1.0f / s;
}

// ============================================================================
// Kernel 4: attn_weights[b,t,s] = (1/H) sum_h expS[bh,t,s] * rinv[bh,t].
// One block (512 thr) per (b,t); thread owns 4 halves -> float4 out.
// ============================================================================
__global__ void headmean_kernel(float* __restrict__ attnw) {
    const int bt = blockIdx.x, b = bt >> 11, t = bt & (Tt - 1);
    const int c = threadIdx.x;                 // 0..511, 4 halves each
    float4 s = make_float4(0.f, 0.f, 0.f, 0.f);
#pragma unroll
    for (int h = 0; h < Hh; h++) {
        const int bh = b * Hh + h;
        const float iv = g_rinv[(size_t)bh * Tt + t];
        const uint2 raw = ((const uint2*)(g_sh + ((size_t)bh * Tt + t) * Tt))[c];
        const float2 f0 = __half22float2(*(const __half2*)&raw.x);
        const float2 f1 = __half22float2(*(const __half2*)&raw.y);
        s.x += f0.x * iv; s.y += f0.y * iv; s.z += f1.x * iv; s.w += f1.y * iv;
    }
    const float m = 1.0f / (float)Hh;
    s.x *= m; s.y *= m; s.z *= m; s.w *= m;
    ((float4*)(attnw + (size_t)bt * Tt))[c] = s;
}

// ============================================================================
// Kernel 5: AV.  D(128x64) = expS(128xTt) . Vt(64xTt)^T, scaled by rinv.
// grid (16, 1, BH), 256 thr. Writes (t*B+b, h*64+hd) fp16 layout.
// ============================================================================
__global__ void __launch_bounds__(256) av_kernel() {
    const int bh = blockIdx.z;
    const int m0 = blockIdx.x * 128;

    float acc[2][4][4] = {};
    gemm_nt_f16<64>(g_sh + (size_t)bh * Tt * Tt + (size_t)m0 * Tt,
                    g_vth + (size_t)bh * HDd * Tt, Tt, Tt, Tt, acc);

    const int lane = threadIdx.x & 31, g = lane >> 2, q = lane & 3;
    const int w = threadIdx.x >> 5, wm = w & 3, wn = w >> 2;
    const int b = bh >> 4, h = bh & 15;

#pragma unroll
    for (int i = 0; i < 2; i++) {
#pragma unroll
        for (int ch = 0; ch < 2; ch++) {
            const int t = m0 + wm * 32 + i * 16 + ch * 8 + g;
            const float iv = g_rinv[(size_t)bh * Tt + t];
#pragma unroll
            for (int j = 0; j < 4; j++) {
                const int col = wn * 32 + j * 8 + q * 2;
                *(__half2*)&g_aoh[((size_t)t * Bb + b) * Ee + h * HDd + col] =
                    __floats2half2_rn(acc[i][j][ch * 2 + 0] * iv,
                                      acc[i][j][ch * 2 + 1] * iv);
            }
        }
    }
}

// ============================================================================
// Kernel 6: out projection -> d_out (fp32). grid (MR/128, Ee/128), 256 thr.
// ============================================================================
__global__ void __launch_bounds__(256) outproj_kernel(const float* __restrict__ ob,
                                                      float* __restrict__ out) {
    const int m0 = blockIdx.x * 128, n0 = blockIdx.y * 128;
    float acc[2][8][4] = {};
    gemm_nt_f16<128>(g_aoh + (size_t)m0 * Ee, g_owh + (size_t)n0 * Ee, Ee, Ee, Ee, acc);

    const int lane = threadIdx.x & 31, g = lane >> 2, q = lane & 3;
    const int w = threadIdx.x >> 5, wm = w & 3, wn = w >> 2;

#pragma unroll
    for (int i = 0; i < 2; i++) {
#pragma unroll
        for (int ch = 0; ch < 2; ch++) {
            const int r = m0 + wm * 32 + i * 16 + ch * 8 + g;
#pragma unroll
            for (int j = 0; j < 8; j++) {
                const int o = n0 + wn * 64 + j * 8 + q * 2;
                float2 p = make_float2(acc[i][j][ch * 2 + 0] + ob[o],
                                       acc[i][j][ch * 2 + 1] + ob[o + 1]);
                *(float2*)&out[(size_t)r * Ee + o] = p;
            }
        }
    }
}

// ============================================================================
extern "C" void kernel_launch(void* const* d_in, const int* in_sizes, int n_in,
                              void* d_out, int out_size) {
    const float* query = (const float*)d_in[0];
    const float* key   = (const float*)d_in[1];
    const float* value = (const float*)d_in[2];
    const float* ipw   = (const float*)d_in[3];   // (3E, E)
    const float* ipb   = (const float*)d_in[4];   // (3E,)
    const float* ow    = (const float*)d_in[5];   // (E, E)
    const float* ob    = (const float*)d_in[6];   // (E,)
    // d_in[7..12]: gate params — provably unused (TOPK == E -> all-ones mask).
    (void)in_sizes; (void)n_in; (void)out_size;

    float* out   = (float*)d_out;                     // attn_output (T,B,E)
    float* attnw = out + (size_t)Tt * Bb * Ee;        // attn_weights (B,T,T)

    prep_kernel   <<<16384, 256>>>(query, key, value, ipw, ow);
    qkv_kernel    <<<dim3(MR / 128, Ee / 128, 3), 256>>>(ipb);
    scores_kernel <<<dim3(Tt / 128, Tt / 128, BH), 256>>>();
    rinv_kernel   <<<(BH * Tt) / 256, 256>>>();
    headmean_kernel<<<Bb * Tt, 512>>>(attnw);
    av_kernel     <<<dim3(Tt / 128, 1, BH), 256>>>();
    outproj_kernel<<<dim3(MR / 128, Ee / 128), 256>>>(ob, out);
}

// round 10
// speedup vs baseline: 1.5004x; 1.1705x over previous
#include <cuda_runtime.h>
#include <cuda_fp16.h>
#include <math.h>
#include <stdint.h>

// Problem constants
#define Tt  2048
#define Bb  2
#define Ee  1024
#define Hh  16
#define HDd 64
#define BH  32          // Bb*Hh
#define MR  4096        // Tt*Bb rows

// -------- device scratch (allocation-free: static device globals) ----------
__device__ __align__(16) __half g_xh[3][(size_t)MR * Ee];    // 24 MB fp16 q/k/v inputs
__device__ __align__(16) __half g_wh[(size_t)3 * Ee * Ee];   //  6 MB fp16 in_proj_w
__device__ __align__(16) __half g_owh[(size_t)Ee * Ee];      //  2 MB fp16 out_w
__device__ __align__(16) __half g_qh[(size_t)BH * Tt * HDd]; //  8 MB (bh,t,hd), q*0.125
__device__ __align__(16) __half g_kh[(size_t)BH * Tt * HDd]; //  8 MB
__device__ __align__(16) __half g_vth[(size_t)BH * HDd * Tt];//  8 MB (bh,hd,t)
__device__ __align__(16) __half g_sh[(size_t)BH * Tt * Tt];  // 256 MB unnormalized exp(scores)
__device__ __align__(16) __half g_aoh[(size_t)MR * Ee];      //  8 MB rows = t*B+b
__device__ __align__(16) float  g_part[(size_t)BH * Tt * 32];//  8 MB rowsum partials
__device__            float  g_rinv[(size_t)BH * Tt];        // 1/rowsum

// ============================================================================
// fp16 mma m16n8k16 + ldmatrix helpers
// ============================================================================
__device__ __forceinline__ void mma16(float c[4], const uint32_t a[4],
                                      uint32_t b0, uint32_t b1) {
    asm volatile(
        "mma.sync.aligned.m16n8k16.row.col.f32.f16.f16.f32 "
        "{%0,%1,%2,%3}, {%4,%5,%6,%7}, {%8,%9}, {%0,%1,%2,%3};"
        : "+f"(c[0]), "+f"(c[1]), "+f"(c[2]), "+f"(c[3])
        : "r"(a[0]), "r"(a[1]), "r"(a[2]), "r"(a[3]), "r"(b0), "r"(b1));
}
__device__ __forceinline__ void ldsm4(uint32_t r[4], uint32_t addr) {
    asm volatile("ldmatrix.sync.aligned.m8n8.x4.shared.b16 {%0,%1,%2,%3}, [%4];"
        : "=r"(r[0]), "=r"(r[1]), "=r"(r[2]), "=r"(r[3]) : "r"(addr));
}

// ============================================================================
// NT fp16 tensor-core GEMM core (ldmatrix edition).
//   C[m,n] = sum_k A[m,k] * B[n,k]   (both K-contiguous row-major, fp16)
// Block 256 thr (8 warps, 4x2). Block tile 128 x BN (64|128). Warp 32 x BN/2.
// K chunked by 32 halves, register double-buffered global loads.
// smem pitch P=40 halves: ldmatrix rows (80B) land on distinct 16B groups.
// ============================================================================
template<int BN>
__device__ __forceinline__ void gemm_nt_f16(
    const __half* __restrict__ A, const __half* __restrict__ B,
    int lda, int ldb, int K, __half* sA, __half* sB,
    float acc[2][BN / 16][4])
{
    constexpr int NT  = BN / 16;
    constexpr int NJJ = BN / 32;          // x4 B-loads per k16 per warp
    constexpr int P   = 40;
    constexpr int BPASS = BN / 64;

    const int tid = threadIdx.x, lane = tid & 31;
    const int w = tid >> 5, wm = w & 3, wn = w >> 2;
    const int lr = lane & 7, sel = lane >> 3;

    // ldmatrix per-lane addresses.
    // A x4 matrices: 0:(m,k) 1:(m+8,k) 2:(m,k+8) 3:(m+8,k+8) -> a0..a3
    // B x4 matrices: 0:(n,k) 1:(n,k+8) 2:(n+8,k) 3:(n+8,k+8) -> b0/b1 x 2 ntiles
    const uint32_t sAu = (uint32_t)__cvta_generic_to_shared(sA);
    const uint32_t sBu = (uint32_t)__cvta_generic_to_shared(sB);
    uint32_t aA[2], aB[NJJ];
#pragma unroll
    for (int i = 0; i < 2; i++)
        aA[i] = sAu + (uint32_t)(((wm * 32 + i * 16 + lr + (sel & 1) * 8) * P
                                  + (sel >> 1) * 8) * 2);
#pragma unroll
    for (int jj = 0; jj < NJJ; jj++)
        aB[jj] = sBu + (uint32_t)(((wn * (BN / 2) + jj * 16 + lr + (sel >> 1) * 8) * P
                                   + (sel & 1) * 8) * 2);

    const int r0 = tid >> 2;              // 0..63
    const int c0 = (tid & 3) * 8;         // halves (16B groups)
    const __half* Ap = A + (size_t)r0 * lda + c0;
    const __half* Bp = B + (size_t)r0 * ldb + c0;

    float4 ra[2], rb[BPASS];
    ra[0] = *(const float4*)Ap;
    ra[1] = *(const float4*)(Ap + (size_t)64 * lda);
#pragma unroll
    for (int p = 0; p < BPASS; p++) rb[p] = *(const float4*)(Bp + (size_t)(p * 64) * ldb);

    for (int k0 = 0; k0 < K; k0 += 32) {
        *(float4*)&sA[(r0     ) * P + c0] = ra[0];
        *(float4*)&sA[(r0 + 64) * P + c0] = ra[1];
#pragma unroll
        for (int p = 0; p < BPASS; p++)
            *(float4*)&sB[(r0 + p * 64) * P + c0] = rb[p];
        __syncthreads();

        if (k0 + 32 < K) {                // prefetch next chunk
            const __half* An = Ap + k0 + 32;
            const __half* Bn = Bp + k0 + 32;
            ra[0] = *(const float4*)An;
            ra[1] = *(const float4*)(An + (size_t)64 * lda);
#pragma unroll
            for (int p = 0; p < BPASS; p++)
                rb[p] = *(const float4*)(Bn + (size_t)(p * 64) * ldb);
        }

#pragma unroll
        for (int kb = 0; kb < 2; kb++) {  // two k16 steps (byte offset 32)
            uint32_t af[2][4];
            ldsm4(af[0], aA[0] + kb * 32);
            ldsm4(af[1], aA[1] + kb * 32);
            uint32_t bf[NJJ][4];
#pragma unroll
            for (int jj = 0; jj < NJJ; jj++) ldsm4(bf[jj], aB[jj] + kb * 32);
#pragma unroll
            for (int j = 0; j < NT; j++) {
                const uint32_t* bp = bf[j >> 1];
                const int o = (j & 1) * 2;
                mma16(acc[0][j], af[0], bp[o], bp[o + 1]);
                mma16(acc[1][j], af[1], bp[o], bp[o + 1]);
            }
        }
        __syncthreads();
    }
}
// C fragment coords: row = wm*32 + i*16 + ch*8 + g ; col = wn*(BN/2) + j*8 + q*2 (+parity)

// ============================================================================
// Kernel 0: fp32 -> fp16 conversion of inputs + weights (one pass).
// Gate params (d_in 7..12) are provably unused: TOPK == E -> all-ones mask,
// so every DGL layer is a plain affine projection.
// ============================================================================
__global__ void prep_kernel(const float* __restrict__ q, const float* __restrict__ k,
                            const float* __restrict__ v, const float* __restrict__ w,
                            const float* __restrict__ ow) {
    const size_t i  = (size_t)blockIdx.x * 256 + threadIdx.x;  // float4 index
    const size_t NX = (size_t)MR * Ee / 4;
    const size_t NW = (size_t)3 * Ee * Ee / 4;
    float4 x; __half* dst;
    if (i < NX)          { x = ((const float4*)q)[i];          dst = g_xh[0] + i * 4; }
    else if (i < 2 * NX) { x = ((const float4*)k)[i - NX];     dst = g_xh[1] + (i - NX) * 4; }
    else if (i < 3 * NX) { x = ((const float4*)v)[i - 2 * NX]; dst = g_xh[2] + (i - 2 * NX) * 4; }
    else if (i < 3 * NX + NW) {
        size_t j = i - 3 * NX;      x = ((const float4*)w)[j];  dst = g_wh + j * 4;
    } else {
        size_t j = i - 3 * NX - NW; x = ((const float4*)ow)[j]; dst = g_owh + j * 4;
    }
    *(__half2*)(dst)     = __floats2half2_rn(x.x, x.y);
    *(__half2*)(dst + 2) = __floats2half2_rn(x.z, x.w);
}

// ============================================================================
// Kernel 1: QKV projection. grid (MR/128, Ee/128, 3), 256 thr.
// ============================================================================
__global__ void __launch_bounds__(256, 2) qkv_kernel(const float* __restrict__ bias) {
    __shared__ __align__(16) __half sh[10240];
    const int mat = blockIdx.z;
    const int m0 = blockIdx.x * 128, n0 = blockIdx.y * 128;
    const float* bp = bias + mat * Ee;

    float acc[2][8][4] = {};
    gemm_nt_f16<128>(g_xh[mat] + (size_t)m0 * Ee,
                     g_wh + (size_t)mat * Ee * Ee + (size_t)n0 * Ee,
                     Ee, Ee, Ee, sh, sh + 5120, acc);

    const int lane = threadIdx.x & 31, g = lane >> 2, q = lane & 3;
    const int w = threadIdx.x >> 5, wm = w & 3, wn = w >> 2;

#pragma unroll
    for (int i = 0; i < 2; i++) {
#pragma unroll
        for (int ch = 0; ch < 2; ch++) {
            const int r = m0 + wm * 32 + i * 16 + ch * 8 + g;  // = t*B + b
            const int t = r >> 1, b = r & 1;
#pragma unroll
            for (int j = 0; j < 8; j++) {
                const int o = n0 + wn * 64 + j * 8 + q * 2;
                float v0 = acc[i][j][ch * 2 + 0] + bp[o];
                float v1 = acc[i][j][ch * 2 + 1] + bp[o + 1];
                const int h = o >> 6, hd = o & 63;
                const int bh = b * Hh + h;
                if (mat == 0) {
                    *(__half2*)&g_qh[((size_t)bh * Tt + t) * HDd + hd] =
                        __floats2half2_rn(v0 * 0.125f, v1 * 0.125f);
                } else if (mat == 1) {
                    *(__half2*)&g_kh[((size_t)bh * Tt + t) * HDd + hd] =
                        __floats2half2_rn(v0, v1);
                } else {
                    g_vth[((size_t)bh * HDd + hd    ) * Tt + t] = __float2half_rn(v0);
                    g_vth[((size_t)bh * HDd + hd + 1) * Tt + t] = __float2half_rn(v1);
                }
            }
        }
    }
}

// ============================================================================
// Kernel 2: scores + exp + rowsum partials, smem-staged coalesced store.
// Unnormalized exp is safe: logits are O(1).
// grid (16, 16, BH), 256 thr.
// ============================================================================
__global__ void __launch_bounds__(256, 2) scores_kernel() {
    __shared__ __align__(16) __half sh[17408];      // GEMM bufs then 128x136 staging
    const int bh = blockIdx.z;
    const int m0 = blockIdx.x * 128, n0 = blockIdx.y * 128;

    float acc[2][8][4] = {};
    gemm_nt_f16<128>(g_qh + (size_t)bh * Tt * HDd + (size_t)m0 * HDd,
                     g_kh + (size_t)bh * Tt * HDd + (size_t)n0 * HDd,
                     HDd, HDd, HDd, sh, sh + 5120, acc);

    const int tid = threadIdx.x;
    const int lane = tid & 31, g = lane >> 2, q = lane & 3;
    const int w = tid >> 5, wm = w & 3, wn = w >> 2;
    constexpr int PS = 136;                          // staging pitch (272B, 16B-aligned)

#pragma unroll
    for (int i = 0; i < 2; i++) {
#pragma unroll
        for (int ch = 0; ch < 2; ch++) {
            const int rl = wm * 32 + i * 16 + ch * 8 + g;
            float rs = 0.f;
#pragma unroll
            for (int j = 0; j < 8; j++) {
                float e0 = __expf(acc[i][j][ch * 2 + 0]);
                float e1 = __expf(acc[i][j][ch * 2 + 1]);
                rs += e0 + e1;
                const int cl = wn * 64 + j * 8 + q * 2;
                *(__half2*)&sh[rl * PS + cl] = __floats2half2_rn(e0, e1);
            }
            rs += __shfl_xor_sync(0xffffffffu, rs, 1);
            rs += __shfl_xor_sync(0xffffffffu, rs, 2);
            if (q == 0)
                g_part[((size_t)bh * Tt + m0 + rl) * 32 + blockIdx.y * 2 + wn] = rs;
        }
    }
    __syncthreads();

    // coalesced store: 16 threads per row emit 256B runs
    __half* S = g_sh + ((size_t)bh * Tt + m0) * Tt + n0;
    const int rr = tid >> 4, cc = (tid & 15) * 8;
#pragma unroll
    for (int it = 0; it < 8; it++) {
        const int r = rr + it * 16;
        *(float4*)&S[(size_t)r * Tt + cc] = *(const float4*)&sh[r * PS + cc];
    }
}

// ============================================================================
// Kernel 3: reduce 32 partials per row -> 1/rowsum.
// ============================================================================
__global__ void rinv_kernel() {
    const int r = blockIdx.x * 256 + threadIdx.x;
    const float* p = &g_part[(size_t)r * 32];
    float s = 0.f;
#pragma unroll
    for (int i = 0; i < 32; i++) s += p[i];
    g_rinv[r] = 1.0f / s;
}

// ============================================================================
// Kernel 4: attn_weights[b,t,s] = (1/H) sum_h expS[bh,t,s] * rinv[bh,t].
// ============================================================================
__global__ void headmean_kernel(float* __restrict__ attnw) {
    const int bt = blockIdx.x, b = bt >> 11, t = bt & (Tt - 1);
    const int c = threadIdx.x;                 // 0..511, 4 halves each
    float4 s = make_float4(0.f, 0.f, 0.f, 0.f);
#pragma unroll
    for (int h = 0; h < Hh; h++) {
        const int bh = b * Hh + h;
        const float iv = g_rinv[(size_t)bh * Tt + t];
        const uint2 raw = ((const uint2*)(g_sh + ((size_t)bh * Tt + t) * Tt))[c];
        const float2 f0 = __half22float2(*(const __half2*)&raw.x);
        const float2 f1 = __half22float2(*(const __half2*)&raw.y);
        s.x += f0.x * iv; s.y += f0.y * iv; s.z += f1.x * iv; s.w += f1.y * iv;
    }
    const float m = 1.0f / (float)Hh;
    s.x *= m; s.y *= m; s.z *= m; s.w *= m;
    ((float4*)(attnw + (size_t)bt * Tt))[c] = s;
}

// ============================================================================
// Kernel 5: AV. D(128x64) = expS(128xTt) . Vt(64xTt)^T, scaled by rinv.
// grid (16, 1, BH), 256 thr. Writes (t*B+b, h*64+hd) fp16 layout.
// ============================================================================
__global__ void __launch_bounds__(256, 2) av_kernel() {
    __shared__ __align__(16) __half sh[7680];
    const int bh = blockIdx.z;
    const int m0 = blockIdx.x * 128;

    float acc[2][4][4] = {};
    gemm_nt_f16<64>(g_sh + (size_t)bh * Tt * Tt + (size_t)m0 * Tt,
                    g_vth + (size_t)bh * HDd * Tt, Tt, Tt, Tt,
                    sh, sh + 5120, acc);

    const int lane = threadIdx.x & 31, g = lane >> 2, q = lane & 3;
    const int w = threadIdx.x >> 5, wm = w & 3, wn = w >> 2;
    const int b = bh >> 4, h = bh & 15;

#pragma unroll
    for (int i = 0; i < 2; i++) {
#pragma unroll
        for (int ch = 0; ch < 2; ch++) {
            const int t = m0 + wm * 32 + i * 16 + ch * 8 + g;
            const float iv = g_rinv[(size_t)bh * Tt + t];
#pragma unroll
            for (int j = 0; j < 4; j++) {
                const int col = wn * 32 + j * 8 + q * 2;
                *(__half2*)&g_aoh[((size_t)t * Bb + b) * Ee + h * HDd + col] =
                    __floats2half2_rn(acc[i][j][ch * 2 + 0] * iv,
                                      acc[i][j][ch * 2 + 1] * iv);
            }
        }
    }
}

// ============================================================================
// Kernel 6: out projection -> d_out (fp32). grid (MR/128, Ee/128), 256 thr.
// ============================================================================
__global__ void __launch_bounds__(256, 2) outproj_kernel(const float* __restrict__ ob,
                                                         float* __restrict__ out) {
    __shared__ __align__(16) __half sh[10240];
    const int m0 = blockIdx.x * 128, n0 = blockIdx.y * 128;
    float acc[2][8][4] = {};
    gemm_nt_f16<128>(g_aoh + (size_t)m0 * Ee, g_owh + (size_t)n0 * Ee,
                     Ee, Ee, Ee, sh, sh + 5120, acc);

    const int lane = threadIdx.x & 31, g = lane >> 2, q = lane & 3;
    const int w = threadIdx.x >> 5, wm = w & 3, wn = w >> 2;

#pragma unroll
    for (int i = 0; i < 2; i++) {
#pragma unroll
        for (int ch = 0; ch < 2; ch++) {
            const int r = m0 + wm * 32 + i * 16 + ch * 8 + g;
#pragma unroll
            for (int j = 0; j < 8; j++) {
                const int o = n0 + wn * 64 + j * 8 + q * 2;
                float2 p = make_float2(acc[i][j][ch * 2 + 0] + ob[o],
                                       acc[i][j][ch * 2 + 1] + ob[o + 1]);
                *(float2*)&out[(size_t)r * Ee + o] = p;
            }
        }
    }
}

// ============================================================================
extern "C" void kernel_launch(void* const* d_in, const int* in_sizes, int n_in,
                              void* d_out, int out_size) {
    const float* query = (const float*)d_in[0];
    const float* key   = (const float*)d_in[1];
    const float* value = (const float*)d_in[2];
    const float* ipw   = (const float*)d_in[3];   // (3E, E)
    const float* ipb   = (const float*)d_in[4];   // (3E,)
    const float* ow    = (const float*)d_in[5];   // (E, E)
    const float* ob    = (const float*)d_in[6];   // (E,)
    // d_in[7..12]: gate params — provably unused (TOPK == E -> all-ones mask).
    (void)in_sizes; (void)n_in; (void)out_size;

    float* out   = (float*)d_out;                     // attn_output (T,B,E)
    float* attnw = out + (size_t)Tt * Bb * Ee;        // attn_weights (B,T,T)

    prep_kernel   <<<16384, 256>>>(query, key, value, ipw, ow);
    qkv_kernel    <<<dim3(MR / 128, Ee / 128, 3), 256>>>(ipb);
    scores_kernel <<<dim3(Tt / 128, Tt / 128, BH), 256>>>();
    rinv_kernel   <<<(BH * Tt) / 256, 256>>>();
    headmean_kernel<<<Bb * Tt, 512>>>(attnw);
    av_kernel     <<<dim3(Tt / 128, 1, BH), 256>>>();
    outproj_kernel<<<dim3(MR / 128, Ee / 128), 256>>>(ob, out);
}